// round 13
// baseline (speedup 1.0000x reference)
#include <cuda_runtime.h>
#include <cstdint>

#define HW_FULL (1024*1024)

#define CSTR 257
#define ZSTR 3084
#define GRID_FLOATS (8*ZSTR)
#define WBUF_Z2 13                       // float2s per z-plane (odd -> conflict-free reads)
#define WBUF_F2 (8*WBUF_Z2)              // 104 float2 = 208 floats per warp
#define SLICE_WARPS 16
#define SLICE_SMEM ((GRID_FLOATS + SLICE_WARPS*WBUF_F2*2)*4)

// ---------------- scratch ----------------
__device__ float d_x1[2*8*128*128];
__device__ float d_x2[2*16*64*64];
__device__ float d_x3[2*32*32*32];
__device__ float d_x4[2*64*16*16];
__device__ float d_g1[2*64*8*8];
__device__ float d_g2[2*64*4*4];
__device__ float d_fc2[2*64];
__device__ float d_loc1[2*64*256];
__device__ float d_loc2[2*64*256];
__device__ float d_co[2*96*256];
__device__ float d_guide[2*HW_FULL];

// ---------------- cp.async helpers ----------------
__device__ __forceinline__ void cp_async4(float* dst_smem, const float* src, bool pred) {
    uint32_t d = (uint32_t)__cvta_generic_to_shared(dst_smem);
    int sz = pred ? 4 : 0;
    asm volatile("cp.async.ca.shared.global [%0], [%1], 4, %2;"
                 :: "r"(d), "l"(src), "r"(sz));
}
__device__ __forceinline__ void cp_async_commit_wait() {
    asm volatile("cp.async.commit_group;");
    asm volatile("cp.async.wait_group 0;" ::: "memory");
}

// ---------------- tiled conv helpers ----------------
__host__ __device__ constexpr int c_ith(int OTH, int S) { return (OTH - 1) * S + 3; }
__host__ __device__ constexpr int c_itwu(int OTW, int S) { return (OTW - 1) * S + 3; }
__host__ __device__ constexpr int c_itw(int OTW, int S) {
    int v = c_itwu(OTW, S); return ((v + 3) / 4) * 4;
}
__host__ __device__ constexpr int c_infl(int CI, int OTH, int OTW, int S) {
    return CI * c_ith(OTH, S) * c_itw(OTW, S);
}
__host__ __device__ constexpr int c_wstr(int CI, int CO_T) { return CO_T * CI * 9 + 1; }
__host__ __device__ constexpr int c_smem_tot(int CI, int OTH, int OTW, int S,
                                             int CGRP, int CO_T) {
    return (c_infl(CI, OTH, OTW, S) + CGRP * c_wstr(CI, CO_T)) * 4;
}
__host__ __device__ constexpr int c_nt(int OTH, int OTW, int PY, int PX, int CGRP) {
    return (OTH / PY) * (OTW / PX) * CGRP;
}

template<int CI, int HI, int WI, int CO, int S, int OTH, int OTW,
         int PY, int PX, int CO_T, int CGRP, int RELU>
__global__ void __launch_bounds__(c_nt(OTH,OTW,PY,PX,CGRP), 1)
conv_tiled(const float* __restrict__ in, const float* __restrict__ w,
           const float* __restrict__ bias, float* __restrict__ out) {
    constexpr int HO = (S == 1) ? HI : HI / 2;
    constexpr int WO = (S == 1) ? WI : WI / 2;
    constexpr int ITH = c_ith(OTH, S);
    constexpr int ITWU = c_itwu(OTW, S);
    constexpr int ITW = c_itw(OTW, S);
    constexpr int NPOSX = OTW / PX;
    constexpr int NPOS = NPOSX * (OTH / PY);
    constexpr int NT = NPOS * CGRP;
    constexpr int TPW = WO / OTW;
    constexpr int INFL = c_infl(CI, OTH, OTW, S);
    constexpr int WSTR = c_wstr(CI, CO_T);
    constexpr int WRAW = CO_T * CI * 9;
    extern __shared__ float sm[];
    float* wsm = sm + INFL;

    int b = blockIdx.z;
    int tile = blockIdx.y;
    int tile_y = tile / TPW, tile_x = tile % TPW;
    int oy0 = tile_y * OTH, ox0 = tile_x * OTW;
    int iy0 = oy0 * S - 1, ix0 = ox0 * S - 1;

    if constexpr (ITW != ITWU) {
        for (int idx = threadIdx.x; idx < CI * ITH * (ITW - ITWU); idx += NT) {
            int pc = idx % (ITW - ITWU);
            int rest = idx / (ITW - ITWU);
            sm[rest * ITW + ITWU + pc] = 0.0f;
        }
    }

    const float* inb = in + (long)b * CI * HI * WI;
    for (int idx = threadIdx.x; idx < CI * ITH * ITWU; idx += NT) {
        int col = idx % ITWU;
        int rest = idx / ITWU;
        int row = rest % ITH;
        int ci = rest / ITH;
        int gy = iy0 + row, gx = ix0 + col;
        bool ok = (gy >= 0 && gy < HI && gx >= 0 && gx < WI);
        const float* src = ok ? (inb + (ci * HI + gy) * WI + gx) : inb;
        cp_async4(&sm[(ci * ITH + row) * ITW + col], src, ok);
    }
    {
        const float* wg = w + (long)(blockIdx.x * CGRP * CO_T) * CI * 9;
        for (int idx = threadIdx.x; idx < CGRP * WRAW; idx += NT) {
            int cg = idx / WRAW, j = idx % WRAW;
            cp_async4(&wsm[cg * WSTR + j], wg + idx, true);
        }
    }
    cp_async_commit_wait();
    __syncthreads();

    int t = threadIdx.x;
    int pos = t % NPOS;
    int cg = t / NPOS;
    int px0 = (pos % NPOSX) * PX, py0 = (pos / NPOSX) * PY;
    int co0 = (blockIdx.x * CGRP + cg) * CO_T;
    const float* wbase = wsm + cg * WSTR;

    constexpr int IR = (PY - 1) * S + 3;
    constexpr int IC = (PX - 1) * S + 3;

    float acc[CO_T][PY][PX];
    #pragma unroll
    for (int a = 0; a < CO_T; a++)
        #pragma unroll
        for (int i = 0; i < PY; i++)
            #pragma unroll
            for (int j = 0; j < PX; j++) acc[a][i][j] = 0.0f;

    #pragma unroll 2
    for (int ci = 0; ci < CI; ci++) {
        float r[IR][IC];
        const float* base = &sm[(ci * ITH + py0 * S) * ITW + px0 * S];
        #pragma unroll
        for (int i = 0; i < IR; i++) {
            const float* rowp = base + i * ITW;
            if constexpr (S == 2 && PX == 2) {
                float4 a = *(const float4*)rowp;
                float  e = rowp[4];
                r[i][0] = a.x; r[i][1] = a.y; r[i][2] = a.z; r[i][3] = a.w; r[i][4] = e;
            } else if constexpr (S == 1 && PX == 2) {
                float2 a = *(const float2*)rowp;
                float2 c = *(const float2*)(rowp + 2);
                r[i][0] = a.x; r[i][1] = a.y; r[i][2] = c.x; r[i][3] = c.y;
            } else if constexpr (S == 2 && PX == 1) {
                float2 a = *(const float2*)rowp;
                r[i][0] = a.x; r[i][1] = a.y; r[i][2] = rowp[2];
            } else {
                #pragma unroll
                for (int j = 0; j < IC; j++) r[i][j] = rowp[j];
            }
        }
        #pragma unroll
        for (int ct = 0; ct < CO_T; ct++) {
            const float* wp = wbase + (ct * CI + ci) * 9;
            #pragma unroll
            for (int ky = 0; ky < 3; ky++)
                #pragma unroll
                for (int kx = 0; kx < 3; kx++) {
                    float wv = wp[ky * 3 + kx];
                    #pragma unroll
                    for (int py = 0; py < PY; py++)
                        #pragma unroll
                        for (int pxx = 0; pxx < PX; pxx++)
                            acc[ct][py][pxx] = fmaf(wv, r[py * S + ky][pxx * S + kx], acc[ct][py][pxx]);
                }
        }
    }

    #pragma unroll
    for (int ct = 0; ct < CO_T; ct++) {
        float bv = bias ? __ldg(bias + co0 + ct) : 0.0f;
        #pragma unroll
        for (int py = 0; py < PY; py++)
            #pragma unroll
            for (int pxx = 0; pxx < PX; pxx++) {
                int oy = oy0 + py0 + py, ox = ox0 + px0 + pxx;
                float v = acc[ct][py][pxx] + bv;
                if (RELU) v = fmaxf(v, 0.0f);
                out[((long)(b * CO + co0 + ct) * HO + oy) * WO + ox] = v;
            }
    }
}

// ---------------- fused FC chain ----------------
__global__ void __launch_bounds__(256, 1)
fc_fused_kernel(const float* __restrict__ in,
                const float* __restrict__ w0, const float* __restrict__ b0,
                const float* __restrict__ w1, const float* __restrict__ b1,
                const float* __restrict__ w2, const float* __restrict__ b2,
                float* __restrict__ out) {
    __shared__ float sin[1024];
    __shared__ float s1[256];
    __shared__ float s2[128];
    int b = blockIdx.x;
    int t = threadIdx.x;
    for (int i = t; i < 1024; i += 256)
        cp_async4(&sin[i], in + b * 1024 + i, true);
    cp_async_commit_wait();
    __syncthreads();
    {
        const float4* wr = (const float4*)(w0 + t * 1024);
        const float4* sp = (const float4*)sin;
        float acc = 0.0f;
        #pragma unroll 8
        for (int i = 0; i < 256; i++) {
            float4 wv = __ldg(wr + i);
            float4 xv = sp[i];
            acc = fmaf(wv.x, xv.x, fmaf(wv.y, xv.y, fmaf(wv.z, xv.z, fmaf(wv.w, xv.w, acc))));
        }
        s1[t] = fmaxf(acc + __ldg(b0 + t), 0.0f);
    }
    __syncthreads();
    if (t < 128) {
        const float4* wr = (const float4*)(w1 + t * 256);
        const float4* sp = (const float4*)s1;
        float acc = 0.0f;
        #pragma unroll 8
        for (int i = 0; i < 64; i++) {
            float4 wv = __ldg(wr + i);
            float4 xv = sp[i];
            acc = fmaf(wv.x, xv.x, fmaf(wv.y, xv.y, fmaf(wv.z, xv.z, fmaf(wv.w, xv.w, acc))));
        }
        s2[t] = fmaxf(acc + __ldg(b1 + t), 0.0f);
    }
    __syncthreads();
    if (t < 64) {
        const float4* wr = (const float4*)(w2 + t * 128);
        const float4* sp = (const float4*)s2;
        float acc = 0.0f;
        #pragma unroll 8
        for (int i = 0; i < 32; i++) {
            float4 wv = __ldg(wr + i);
            float4 xv = sp[i];
            acc = fmaf(wv.x, xv.x, fmaf(wv.y, xv.y, fmaf(wv.z, xv.z, fmaf(wv.w, xv.w, acc))));
        }
        out[b * 64 + t] = acc + __ldg(b2 + t);
    }
}

// ---------------- fusion + 1x1 prediction ----------------
__global__ void co_kernel(const float* __restrict__ loc, const float* __restrict__ g,
                          const float* __restrict__ pw, const float* __restrict__ pb,
                          float* __restrict__ co, int B) {
    int idx = blockIdx.x * blockDim.x + threadIdx.x;
    int total = B * 96 * 64;
    if (idx >= total) return;
    int p4 = idx & 63;
    int o = (idx >> 6) % 96;
    int b = idx / (96 * 64);
    float bv = __ldg(pb + o);
    float4 acc = make_float4(bv, bv, bv, bv);
    const float* gb = g + b * 64;
    const float* lb = loc + b * 64 * 256 + p4 * 4;
    const float* wb = pw + o * 64;
    #pragma unroll 4
    for (int c = 0; c < 64; c++) {
        float4 l = *(const float4*)(lb + c * 256);
        float gv = __ldg(gb + c);
        float wv = __ldg(wb + c);
        acc.x = fmaf(wv, fmaxf(l.x + gv, 0.0f), acc.x);
        acc.y = fmaf(wv, fmaxf(l.y + gv, 0.0f), acc.y);
        acc.z = fmaf(wv, fmaxf(l.z + gv, 0.0f), acc.z);
        acc.w = fmaf(wv, fmaxf(l.w + gv, 0.0f), acc.w);
    }
    *(float4*)(co + ((long)(b * 96 + o) << 8) + p4 * 4) = acc;
}

// ---------------- guide map (standalone, params in registers) ----------------
__global__ void guide_kernel(const float* __restrict__ img,
                             const float* __restrict__ ccm_w, const float* __restrict__ ccm_b,
                             const float* __restrict__ shifts, const float* __restrict__ slopes,
                             const float* __restrict__ proj_w, const float* __restrict__ proj_b,
                             float* __restrict__ guide, int B) {
    float ccm[9], cb[3], sh[48], psl[48];
    #pragma unroll
    for (int i = 0; i < 9; i++) ccm[i] = __ldg(ccm_w + i);
    #pragma unroll
    for (int i = 0; i < 3; i++) cb[i] = __ldg(ccm_b + i);
    #pragma unroll
    for (int i = 0; i < 48; i++) sh[i] = __ldg(shifts + i);
    #pragma unroll
    for (int c = 0; c < 3; c++) {
        float pwv = __ldg(proj_w + c);
        #pragma unroll
        for (int k = 0; k < 16; k++) psl[c * 16 + k] = pwv * __ldg(slopes + c * 16 + k);
    }
    float pbv = __ldg(proj_b);

    int total4 = (B * HW_FULL) >> 2;
    int stride = gridDim.x * blockDim.x;
    for (int i4 = blockIdx.x * blockDim.x + threadIdx.x; i4 < total4; i4 += stride) {
        int b = i4 >> 18;
        int p4 = i4 & ((1 << 18) - 1);
        long pb_off = ((long)(b * 3) << 20) + ((long)p4 << 2);
        float4 r4 = __ldg((const float4*)(img + pb_off));
        float4 g4 = __ldg((const float4*)(img + pb_off + HW_FULL));
        float4 b4 = __ldg((const float4*)(img + pb_off + 2 * HW_FULL));
        float ra[4] = {r4.x, r4.y, r4.z, r4.w};
        float ga[4] = {g4.x, g4.y, g4.z, g4.w};
        float ba[4] = {b4.x, b4.y, b4.z, b4.w};
        float oa[4];
        #pragma unroll
        for (int j = 0; j < 4; j++) {
            float acc = pbv;
            #pragma unroll
            for (int c = 0; c < 3; c++) {
                float v = fmaf(ccm[c*3+0], ra[j], fmaf(ccm[c*3+1], ga[j],
                          fmaf(ccm[c*3+2], ba[j], cb[c])));
                #pragma unroll
                for (int k = 0; k < 16; k++)
                    acc = fmaf(psl[c*16+k], fmaxf(v - sh[c*16+k], 0.0f), acc);
            }
            oa[j] = fminf(fmaxf(acc, 0.0f), 1.0f);
        }
        float4 o4 = make_float4(oa[0], oa[1], oa[2], oa[3]);
        *(float4*)(guide + ((long)b << 20) + ((long)p4 << 2)) = o4;
    }
}

// ---------------- bilateral slice + affine apply (float2 wbuf, 512 threads) ----------------
__global__ void __launch_bounds__(SLICE_WARPS*32, 1)
slice_kernel(const float* __restrict__ img, const float* __restrict__ guide,
             const float* __restrict__ co, float* __restrict__ out,
             int pxPerBlock) {
    extern __shared__ float sm[];
    int b = blockIdx.z;
    const float* cob = co + b * 96 * 256;
    for (int i = threadIdx.x; i < 96 * 256; i += blockDim.x) {
        int ch = i >> 8;
        int p = i & 255;
        int z = ch / 12, c = ch % 12;
        cp_async4(&sm[z * ZSTR + c * CSTR + p], cob + i, true);
    }
    cp_async_commit_wait();
    __syncthreads();

    int lane = threadIdx.x & 31;
    float2* wbuf = (float2*)(sm + GRID_FLOATS) + (threadIdx.x >> 5) * WBUF_F2;

    int base = blockIdx.x * pxPerBlock;
    const float* imr = img + ((long)(b * 3 + 0) << 20);
    const float* img1 = img + ((long)(b * 3 + 1) << 20);
    const float* imb = img + ((long)(b * 3 + 2) << 20);
    const float* gd = guide + ((long)b << 20);
    float* o0 = out + ((long)(b * 3 + 0) << 20);
    float* o1 = out + ((long)(b * 3 + 1) << 20);
    float* o2 = out + ((long)(b * 3 + 2) << 20);

    for (int t = threadIdx.x; t < pxPerBlock; t += blockDim.x) {
        int px = base + t;
        int xx = px & 1023;
        int yy = px >> 10;
        float xs = (xx + 0.5f) * (1.0f / 64.0f) - 0.5f;
        float ys = (yy + 0.5f) * (1.0f / 64.0f) - 0.5f;
        float fx = floorf(xs), fy = floorf(ys);
        float wx1 = xs - fx, wx0 = 1.0f - wx1;     // per-lane
        float wy1 = ys - fy, wy0 = 1.0f - wy1;     // warp-uniform
        int ix = (int)fx, iy = (int)fy;
        int x0 = min(max(ix, 0), 15), x1 = min(max(ix + 1, 0), 15);
        int y0 = min(max(iy, 0), 15), y1 = min(max(iy + 1, 0), 15);
        int o00 = y0 * 16 + x0, o10 = y1 * 16 + x0;
        int o01 = y0 * 16 + x1, o11 = y1 * 16 + x1;

        // cooperative y-interp (warp-uniform weights); store (A,B) adjacent
        #pragma unroll
        for (int rr = 0; rr < 3; rr++) {
            int j = lane + 32 * rr;
            int z = j / 12, c = j % 12;
            const float* gbase = sm + z * ZSTR + c * CSTR;
            float A  = wy0 * gbase[o00] + wy1 * gbase[o10];
            float Bv = wy0 * gbase[o01] + wy1 * gbase[o11];
            wbuf[z * WBUF_Z2 + c] = make_float2(A, Bv);
        }
        __syncwarp();

        float gz = gd[px] * 8.0f - 0.5f;
        float fz = floorf(gz);
        float wz1 = gz - fz, wz0 = 1.0f - wz1;
        int iz = (int)fz;
        int z0 = min(max(iz, 0), 7), z1 = min(max(iz + 1, 0), 7);
        const float2* p0 = wbuf + z0 * WBUF_Z2;
        const float2* p1 = wbuf + z1 * WBUF_Z2;
        float cf[12];
        #pragma unroll
        for (int c = 0; c < 12; c++) {
            float2 ab0 = p0[c];
            float2 ab1 = p1[c];
            float v0 = wx0 * ab0.x + wx1 * ab0.y;
            float v1 = wx0 * ab1.x + wx1 * ab1.y;
            cf[c] = wz0 * v0 + wz1 * v1;
        }
        __syncwarp();

        float r = imr[px], g = img1[px], bl = imb[px];
        float v0 = fmaf(cf[0], r, fmaf(cf[1],  g, fmaf(cf[2],  bl, cf[3])));
        float v1 = fmaf(cf[4], r, fmaf(cf[5],  g, fmaf(cf[6],  bl, cf[7])));
        float v2 = fmaf(cf[8], r, fmaf(cf[9],  g, fmaf(cf[10], bl, cf[11])));
        o0[px] = fminf(fmaxf(v0, 0.0f), 1.0f);
        o1[px] = fminf(fmaxf(v1, 0.0f), 1.0f);
        o2[px] = fminf(fmaxf(v2, 0.0f), 1.0f);
    }
}

// ---------------- driver (single stream) ----------------
extern "C" void kernel_launch(void* const* d_in, const int* in_sizes, int n_in,
                              void* d_out, int out_size) {
    const float* image_lowres  = (const float*)d_in[0];
    const float* image_fullres = (const float*)d_in[1];
    const float* sw0 = (const float*)d_in[2];  const float* sb0 = (const float*)d_in[3];
    const float* sw1 = (const float*)d_in[4];  const float* sb1 = (const float*)d_in[5];
    const float* sw2 = (const float*)d_in[6];  const float* sb2 = (const float*)d_in[7];
    const float* sw3 = (const float*)d_in[8];  const float* sb3 = (const float*)d_in[9];
    const float* gw0 = (const float*)d_in[10]; const float* gb0 = (const float*)d_in[11];
    const float* gw1 = (const float*)d_in[12]; const float* gb1 = (const float*)d_in[13];
    const float* fw0 = (const float*)d_in[14]; const float* fb0 = (const float*)d_in[15];
    const float* fw1 = (const float*)d_in[16]; const float* fb1 = (const float*)d_in[17];
    const float* fw2 = (const float*)d_in[18]; const float* fb2 = (const float*)d_in[19];
    const float* lw0 = (const float*)d_in[20]; const float* lb0 = (const float*)d_in[21];
    const float* lw1 = (const float*)d_in[22];
    const float* pw  = (const float*)d_in[23]; const float* pb  = (const float*)d_in[24];
    const float* ccm_w = (const float*)d_in[25]; const float* ccm_b = (const float*)d_in[26];
    const float* shifts = (const float*)d_in[27];
    const float* slopes = (const float*)d_in[28];
    const float* proj_w = (const float*)d_in[29];
    const float* proj_b = (const float*)d_in[30];

    int B = in_sizes[1] / (3 * 1024 * 1024);

    float *x1, *x2, *x3, *x4, *g1, *g2, *fc2, *loc1, *loc2, *co, *guide;
    cudaGetSymbolAddress((void**)&x1, d_x1);
    cudaGetSymbolAddress((void**)&x2, d_x2);
    cudaGetSymbolAddress((void**)&x3, d_x3);
    cudaGetSymbolAddress((void**)&x4, d_x4);
    cudaGetSymbolAddress((void**)&g1, d_g1);
    cudaGetSymbolAddress((void**)&g2, d_g2);
    cudaGetSymbolAddress((void**)&fc2, d_fc2);
    cudaGetSymbolAddress((void**)&loc1, d_loc1);
    cudaGetSymbolAddress((void**)&loc2, d_loc2);
    cudaGetSymbolAddress((void**)&co, d_co);
    cudaGetSymbolAddress((void**)&guide, d_guide);

    const int T = 256;
    auto blocks = [](int n, int t) { return (n + t - 1) / t; };

    guide_kernel<<<256, 256>>>(image_fullres, ccm_w, ccm_b, shifts, slopes,
                               proj_w, proj_b, guide, B);

    // ---- splat path ----
    {
        auto k = conv_tiled<3,256,256,8,2, 8,32, 1,2, 2,2, 1>;
        constexpr int sb = c_smem_tot(3,8,32,2,2,2);
        cudaFuncSetAttribute(k, cudaFuncAttributeMaxDynamicSharedMemorySize, sb);
        k<<<dim3(2,64,B), 256, sb>>>(image_lowres, sw0, sb0, x1);
    }
    {
        auto k = conv_tiled<8,128,128,16,2, 8,16, 1,2, 2,4, 1>;
        constexpr int sb = c_smem_tot(8,8,16,2,4,2);
        cudaFuncSetAttribute(k, cudaFuncAttributeMaxDynamicSharedMemorySize, sb);
        k<<<dim3(2,32,B), 256, sb>>>(x1, sw1, sb1, x2);
    }
    {
        auto k = conv_tiled<16,64,64,32,2, 8,16, 1,2, 1,4, 1>;
        constexpr int sb = c_smem_tot(16,8,16,2,4,1);
        cudaFuncSetAttribute(k, cudaFuncAttributeMaxDynamicSharedMemorySize, sb);
        k<<<dim3(8,8,B), 256, sb>>>(x2, sw2, sb2, x3);
    }
    {
        auto k = conv_tiled<32,32,32,64,2, 8,8, 1,2, 1,4, 1>;
        constexpr int sb = c_smem_tot(32,8,8,2,4,1);
        cudaFuncSetAttribute(k, cudaFuncAttributeMaxDynamicSharedMemorySize, sb);
        k<<<dim3(16,4,B), 128, sb>>>(x3, sw3, sb3, x4);
    }
    // ---- global path ----
    {
        auto k = conv_tiled<64,16,16,64,2, 8,8, 1,2, 1,4, 1>;
        constexpr int sb = c_smem_tot(64,8,8,2,4,1);
        cudaFuncSetAttribute(k, cudaFuncAttributeMaxDynamicSharedMemorySize, sb);
        k<<<dim3(16,1,B), 128, sb>>>(x4, gw0, gb0, g1);
    }
    {
        auto k = conv_tiled<64,8,8,64,2, 4,4, 1,2, 1,16, 1>;
        constexpr int sb = c_smem_tot(64,4,4,2,16,1);
        cudaFuncSetAttribute(k, cudaFuncAttributeMaxDynamicSharedMemorySize, sb);
        k<<<dim3(4,1,B), 128, sb>>>(g1, gw1, gb1, g2);
    }
    fc_fused_kernel<<<B, 256>>>(g2, fw0, fb0, fw1, fb1, fw2, fb2, fc2);
    // ---- local path ----
    {
        auto k = conv_tiled<64,16,16,64,1, 8,16, 1,2, 1,4, 1>;
        constexpr int sb = c_smem_tot(64,8,16,1,4,1);
        cudaFuncSetAttribute(k, cudaFuncAttributeMaxDynamicSharedMemorySize, sb);
        k<<<dim3(16,2,B), 256, sb>>>(x4, lw0, lb0, loc1);
    }
    {
        auto k = conv_tiled<64,16,16,64,1, 8,16, 1,2, 1,4, 0>;
        constexpr int sb = c_smem_tot(64,8,16,1,4,1);
        cudaFuncSetAttribute(k, cudaFuncAttributeMaxDynamicSharedMemorySize, sb);
        k<<<dim3(16,2,B), 256, sb>>>(loc1, lw1, nullptr, loc2);
    }
    // ---- fusion + 1x1 prediction ----
    co_kernel<<<blocks(B*96*64, T), T>>>(loc2, fc2, pw, pb, co, B);
    // ---- slice + apply ----
    {
        cudaFuncSetAttribute(slice_kernel, cudaFuncAttributeMaxDynamicSharedMemorySize, SLICE_SMEM);
        int pxPerBlock = 16384;
        dim3 g(HW_FULL / pxPerBlock, 1, B);
        slice_kernel<<<g, SLICE_WARPS*32, SLICE_SMEM>>>(image_fullres, guide, co,
                                                        (float*)d_out, pxPerBlock);
    }
}

// round 14
// speedup vs baseline: 1.2021x; 1.2021x over previous
#include <cuda_runtime.h>
#include <cstdint>

#define HW_FULL (1024*1024)

#define CSTR 257
#define ZSTR 3084
#define GRID_FLOATS (8*ZSTR)
#define WBUF_Z2 13                        // float2s per z-plane (odd -> conflict-free)
#define WBUF_F2 (8*WBUF_Z2)               // 104 float2 per warp
#define SLICE_WARPS 8
#define SLICE_SMEM ((GRID_FLOATS + SLICE_WARPS*WBUF_F2*2)*4)

// ---------------- scratch ----------------
__device__ float d_x1[2*8*128*128];
__device__ float d_x2[2*16*64*64];
__device__ float d_x3[2*32*32*32];
__device__ float d_x4[2*64*16*16];
__device__ float d_g1[2*64*8*8];
__device__ float d_g2[2*64*4*4];
__device__ float d_fc0[2*256];
__device__ float d_fc1[2*128];
__device__ float d_fc2[2*64];
__device__ float d_loc1[2*64*256];
__device__ float d_loc2[2*64*256];
__device__ float d_co[2*96*256];
__device__ float d_guide[2*HW_FULL];

// ---------------- cp.async helpers ----------------
__device__ __forceinline__ void cp_async4(float* dst_smem, const float* src, bool pred) {
    uint32_t d = (uint32_t)__cvta_generic_to_shared(dst_smem);
    int sz = pred ? 4 : 0;
    asm volatile("cp.async.ca.shared.global [%0], [%1], 4, %2;"
                 :: "r"(d), "l"(src), "r"(sz));
}
__device__ __forceinline__ void cp_async_commit_wait() {
    asm volatile("cp.async.commit_group;");
    asm volatile("cp.async.wait_group 0;" ::: "memory");
}

// ---------------- tiled conv helpers ----------------
__host__ __device__ constexpr int c_ith(int OTH, int S) { return (OTH - 1) * S + 3; }
__host__ __device__ constexpr int c_itwu(int OTW, int S) { return (OTW - 1) * S + 3; }
__host__ __device__ constexpr int c_itw(int OTW, int S) {
    int v = c_itwu(OTW, S); return ((v + 3) / 4) * 4;
}
__host__ __device__ constexpr int c_infl(int CI, int OTH, int OTW, int S) {
    return CI * c_ith(OTH, S) * c_itw(OTW, S);
}
__host__ __device__ constexpr int c_wstr(int CI, int CO_T) { return CO_T * CI * 9 + 1; }
__host__ __device__ constexpr int c_smem_tot(int CI, int OTH, int OTW, int S,
                                             int CGRP, int CO_T) {
    return (c_infl(CI, OTH, OTW, S) + CGRP * c_wstr(CI, CO_T)) * 4;
}
__host__ __device__ constexpr int c_nt(int OTH, int OTW, int PY, int PX, int CGRP) {
    return (OTH / PY) * (OTW / PX) * CGRP;
}

template<int CI, int HI, int WI, int CO, int S, int OTH, int OTW,
         int PY, int PX, int CO_T, int CGRP, int RELU>
__global__ void __launch_bounds__(c_nt(OTH,OTW,PY,PX,CGRP), 1)
conv_tiled(const float* __restrict__ in, const float* __restrict__ w,
           const float* __restrict__ bias, float* __restrict__ out) {
    constexpr int HO = (S == 1) ? HI : HI / 2;
    constexpr int WO = (S == 1) ? WI : WI / 2;
    constexpr int ITH = c_ith(OTH, S);
    constexpr int ITWU = c_itwu(OTW, S);
    constexpr int ITW = c_itw(OTW, S);
    constexpr int NPOSX = OTW / PX;
    constexpr int NPOS = NPOSX * (OTH / PY);
    constexpr int NT = NPOS * CGRP;
    constexpr int TPW = WO / OTW;
    constexpr int INFL = c_infl(CI, OTH, OTW, S);
    constexpr int WSTR = c_wstr(CI, CO_T);
    constexpr int WRAW = CO_T * CI * 9;
    extern __shared__ float sm[];
    float* wsm = sm + INFL;

    int b = blockIdx.z;
    int tile = blockIdx.y;
    int tile_y = tile / TPW, tile_x = tile % TPW;
    int oy0 = tile_y * OTH, ox0 = tile_x * OTW;
    int iy0 = oy0 * S - 1, ix0 = ox0 * S - 1;

    if constexpr (ITW != ITWU) {
        for (int idx = threadIdx.x; idx < CI * ITH * (ITW - ITWU); idx += NT) {
            int pc = idx % (ITW - ITWU);
            int rest = idx / (ITW - ITWU);
            sm[rest * ITW + ITWU + pc] = 0.0f;
        }
    }

    const float* inb = in + (long)b * CI * HI * WI;
    for (int idx = threadIdx.x; idx < CI * ITH * ITWU; idx += NT) {
        int col = idx % ITWU;
        int rest = idx / ITWU;
        int row = rest % ITH;
        int ci = rest / ITH;
        int gy = iy0 + row, gx = ix0 + col;
        bool ok = (gy >= 0 && gy < HI && gx >= 0 && gx < WI);
        const float* src = ok ? (inb + (ci * HI + gy) * WI + gx) : inb;
        cp_async4(&sm[(ci * ITH + row) * ITW + col], src, ok);
    }
    {
        const float* wg = w + (long)(blockIdx.x * CGRP * CO_T) * CI * 9;
        for (int idx = threadIdx.x; idx < CGRP * WRAW; idx += NT) {
            int cg = idx / WRAW, j = idx % WRAW;
            cp_async4(&wsm[cg * WSTR + j], wg + idx, true);
        }
    }
    cp_async_commit_wait();
    __syncthreads();

    int t = threadIdx.x;
    int pos = t % NPOS;
    int cg = t / NPOS;
    int px0 = (pos % NPOSX) * PX, py0 = (pos / NPOSX) * PY;
    int co0 = (blockIdx.x * CGRP + cg) * CO_T;
    const float* wbase = wsm + cg * WSTR;

    constexpr int IR = (PY - 1) * S + 3;
    constexpr int IC = (PX - 1) * S + 3;

    float acc[CO_T][PY][PX];
    #pragma unroll
    for (int a = 0; a < CO_T; a++)
        #pragma unroll
        for (int i = 0; i < PY; i++)
            #pragma unroll
            for (int j = 0; j < PX; j++) acc[a][i][j] = 0.0f;

    #pragma unroll 4
    for (int ci = 0; ci < CI; ci++) {
        float r[IR][IC];
        const float* base = &sm[(ci * ITH + py0 * S) * ITW + px0 * S];
        #pragma unroll
        for (int i = 0; i < IR; i++) {
            const float* rowp = base + i * ITW;
            if constexpr (S == 2 && PX == 2) {
                float4 a = *(const float4*)rowp;
                float  e = rowp[4];
                r[i][0] = a.x; r[i][1] = a.y; r[i][2] = a.z; r[i][3] = a.w; r[i][4] = e;
            } else if constexpr (S == 1 && PX == 2) {
                float2 a = *(const float2*)rowp;
                float2 c = *(const float2*)(rowp + 2);
                r[i][0] = a.x; r[i][1] = a.y; r[i][2] = c.x; r[i][3] = c.y;
            } else if constexpr (S == 2 && PX == 1) {
                float2 a = *(const float2*)rowp;
                r[i][0] = a.x; r[i][1] = a.y; r[i][2] = rowp[2];
            } else {
                #pragma unroll
                for (int j = 0; j < IC; j++) r[i][j] = rowp[j];
            }
        }
        #pragma unroll
        for (int ct = 0; ct < CO_T; ct++) {
            const float* wp = wbase + (ct * CI + ci) * 9;
            #pragma unroll
            for (int ky = 0; ky < 3; ky++)
                #pragma unroll
                for (int kx = 0; kx < 3; kx++) {
                    float wv = wp[ky * 3 + kx];
                    #pragma unroll
                    for (int py = 0; py < PY; py++)
                        #pragma unroll
                        for (int pxx = 0; pxx < PX; pxx++)
                            acc[ct][py][pxx] = fmaf(wv, r[py * S + ky][pxx * S + kx], acc[ct][py][pxx]);
                }
        }
    }

    #pragma unroll
    for (int ct = 0; ct < CO_T; ct++) {
        float bv = bias ? __ldg(bias + co0 + ct) : 0.0f;
        #pragma unroll
        for (int py = 0; py < PY; py++)
            #pragma unroll
            for (int pxx = 0; pxx < PX; pxx++) {
                int oy = oy0 + py0 + py, ox = ox0 + px0 + pxx;
                float v = acc[ct][py][pxx] + bv;
                if (RELU) v = fmaxf(v, 0.0f);
                out[((long)(b * CO + co0 + ct) * HO + oy) * WO + ox] = v;
            }
    }
}

// ---------------- fully-connected: one warp per output row ----------------
__global__ void fc_kernel(const float* __restrict__ in, const float* __restrict__ w,
                          const float* __restrict__ bias, float* __restrict__ out,
                          int B, int In, int Out, int relu) {
    int warp = (blockIdx.x * blockDim.x + threadIdx.x) >> 5;
    int lane = threadIdx.x & 31;
    if (warp >= B * Out) return;
    int b = warp / Out;
    int o = warp % Out;
    float acc = 0.0f;
    const float* ib = in + b * In;
    const float* wb = w + o * In;
    for (int i = lane; i < In; i += 32) acc += __ldg(ib + i) * __ldg(wb + i);
    #pragma unroll
    for (int off = 16; off > 0; off >>= 1) acc += __shfl_down_sync(0xffffffffu, acc, off);
    if (lane == 0) {
        acc += __ldg(bias + o);
        if (relu) acc = fmaxf(acc, 0.0f);
        out[warp] = acc;
    }
}

// ---------------- fusion + 1x1 prediction ----------------
__global__ void co_kernel(const float* __restrict__ loc, const float* __restrict__ g,
                          const float* __restrict__ pw, const float* __restrict__ pb,
                          float* __restrict__ co, int B) {
    int idx = blockIdx.x * blockDim.x + threadIdx.x;
    int total = B * 96 * 64;
    if (idx >= total) return;
    int p4 = idx & 63;
    int o = (idx >> 6) % 96;
    int b = idx / (96 * 64);
    float bv = __ldg(pb + o);
    float4 acc = make_float4(bv, bv, bv, bv);
    const float* gb = g + b * 64;
    const float* lb = loc + b * 64 * 256 + p4 * 4;
    const float* wb = pw + o * 64;
    #pragma unroll 4
    for (int c = 0; c < 64; c++) {
        float4 l = *(const float4*)(lb + c * 256);
        float gv = __ldg(gb + c);
        float wv = __ldg(wb + c);
        acc.x = fmaf(wv, fmaxf(l.x + gv, 0.0f), acc.x);
        acc.y = fmaf(wv, fmaxf(l.y + gv, 0.0f), acc.y);
        acc.z = fmaf(wv, fmaxf(l.z + gv, 0.0f), acc.z);
        acc.w = fmaf(wv, fmaxf(l.w + gv, 0.0f), acc.w);
    }
    *(float4*)(co + ((long)(b * 96 + o) << 8) + p4 * 4) = acc;
}

// ---------------- guide map ----------------
__global__ void guide_kernel(const float* __restrict__ img,
                             const float* __restrict__ ccm_w, const float* __restrict__ ccm_b,
                             const float* __restrict__ shifts, const float* __restrict__ slopes,
                             const float* __restrict__ proj_w, const float* __restrict__ proj_b,
                             float* __restrict__ guide, int B) {
    float ccm[9], cb[3], sh[48], psl[48];
    #pragma unroll
    for (int i = 0; i < 9; i++) ccm[i] = __ldg(ccm_w + i);
    #pragma unroll
    for (int i = 0; i < 3; i++) cb[i] = __ldg(ccm_b + i);
    #pragma unroll
    for (int i = 0; i < 48; i++) sh[i] = __ldg(shifts + i);
    #pragma unroll
    for (int c = 0; c < 3; c++) {
        float pwv = __ldg(proj_w + c);
        #pragma unroll
        for (int k = 0; k < 16; k++) psl[c * 16 + k] = pwv * __ldg(slopes + c * 16 + k);
    }
    float pbv = __ldg(proj_b);

    int total4 = (B * HW_FULL) >> 2;
    int stride = gridDim.x * blockDim.x;
    for (int i4 = blockIdx.x * blockDim.x + threadIdx.x; i4 < total4; i4 += stride) {
        int b = i4 >> 18;
        int p4 = i4 & ((1 << 18) - 1);
        long pb_off = ((long)(b * 3) << 20) + ((long)p4 << 2);
        float4 r4 = __ldg((const float4*)(img + pb_off));
        float4 g4 = __ldg((const float4*)(img + pb_off + HW_FULL));
        float4 b4 = __ldg((const float4*)(img + pb_off + 2 * HW_FULL));
        float ra[4] = {r4.x, r4.y, r4.z, r4.w};
        float ga[4] = {g4.x, g4.y, g4.z, g4.w};
        float ba[4] = {b4.x, b4.y, b4.z, b4.w};
        float oa[4];
        #pragma unroll
        for (int j = 0; j < 4; j++) {
            float acc = pbv;
            #pragma unroll
            for (int c = 0; c < 3; c++) {
                float v = fmaf(ccm[c*3+0], ra[j], fmaf(ccm[c*3+1], ga[j],
                          fmaf(ccm[c*3+2], ba[j], cb[c])));
                #pragma unroll
                for (int k = 0; k < 16; k++)
                    acc = fmaf(psl[c*16+k], fmaxf(v - sh[c*16+k], 0.0f), acc);
            }
            oa[j] = fminf(fmaxf(acc, 0.0f), 1.0f);
        }
        float4 o4 = make_float4(oa[0], oa[1], oa[2], oa[3]);
        *(float4*)(guide + ((long)b << 20) + ((long)p4 << 2)) = o4;
    }
}

// ---------------- bilateral slice + affine apply (R8 shape, float2 wbuf) ----------------
__global__ void __launch_bounds__(SLICE_WARPS*32, 1)
slice_kernel(const float* __restrict__ img, const float* __restrict__ guide,
             const float* __restrict__ co, float* __restrict__ out,
             int pxPerBlock) {
    extern __shared__ float sm[];
    int b = blockIdx.z;
    const float* cob = co + b * 96 * 256;
    for (int i = threadIdx.x; i < 96 * 256; i += blockDim.x) {
        int ch = i >> 8;
        int p = i & 255;
        int z = ch / 12, c = ch % 12;
        cp_async4(&sm[z * ZSTR + c * CSTR + p], cob + i, true);
    }
    cp_async_commit_wait();
    __syncthreads();

    int lane = threadIdx.x & 31;
    float2* wbuf = (float2*)(sm + GRID_FLOATS) + (threadIdx.x >> 5) * WBUF_F2;

    int base = blockIdx.x * pxPerBlock;
    const float* imr = img + ((long)(b * 3 + 0) << 20);
    const float* img1 = img + ((long)(b * 3 + 1) << 20);
    const float* imb = img + ((long)(b * 3 + 2) << 20);
    const float* gd = guide + ((long)b << 20);
    float* o0 = out + ((long)(b * 3 + 0) << 20);
    float* o1 = out + ((long)(b * 3 + 1) << 20);
    float* o2 = out + ((long)(b * 3 + 2) << 20);

    for (int t = threadIdx.x; t < pxPerBlock; t += blockDim.x) {
        int px = base + t;
        int xx = px & 1023;
        int yy = px >> 10;
        float xs = (xx + 0.5f) * (1.0f / 64.0f) - 0.5f;
        float ys = (yy + 0.5f) * (1.0f / 64.0f) - 0.5f;
        float fx = floorf(xs), fy = floorf(ys);
        float wx1 = xs - fx, wx0 = 1.0f - wx1;     // per-lane
        float wy1 = ys - fy, wy0 = 1.0f - wy1;     // warp-uniform
        int ix = (int)fx, iy = (int)fy;
        int x0 = min(max(ix, 0), 15), x1 = min(max(ix + 1, 0), 15);
        int y0 = min(max(iy, 0), 15), y1 = min(max(iy + 1, 0), 15);
        int o00 = y0 * 16 + x0, o10 = y1 * 16 + x0;
        int o01 = y0 * 16 + x1, o11 = y1 * 16 + x1;

        // cooperative y-interp (warp-uniform weights); (A,B) adjacent in float2
        #pragma unroll
        for (int rr = 0; rr < 3; rr++) {
            int j = lane + 32 * rr;
            int z = j / 12, c = j % 12;
            const float* gbase = sm + z * ZSTR + c * CSTR;
            float A  = wy0 * gbase[o00] + wy1 * gbase[o10];
            float Bv = wy0 * gbase[o01] + wy1 * gbase[o11];
            wbuf[z * WBUF_Z2 + c] = make_float2(A, Bv);
        }
        __syncwarp();

        float gz = gd[px] * 8.0f - 0.5f;
        float fz = floorf(gz);
        float wz1 = gz - fz, wz0 = 1.0f - wz1;
        int iz = (int)fz;
        int z0 = min(max(iz, 0), 7), z1 = min(max(iz + 1, 0), 7);
        const float2* p0 = wbuf + z0 * WBUF_Z2;
        const float2* p1 = wbuf + z1 * WBUF_Z2;
        float cf[12];
        #pragma unroll
        for (int c = 0; c < 12; c++) {
            float2 ab0 = p0[c];
            float2 ab1 = p1[c];
            float v0 = wx0 * ab0.x + wx1 * ab0.y;
            float v1 = wx0 * ab1.x + wx1 * ab1.y;
            cf[c] = wz0 * v0 + wz1 * v1;
        }
        __syncwarp();

        float r = imr[px], g = img1[px], bl = imb[px];
        float v0 = fmaf(cf[0], r, fmaf(cf[1],  g, fmaf(cf[2],  bl, cf[3])));
        float v1 = fmaf(cf[4], r, fmaf(cf[5],  g, fmaf(cf[6],  bl, cf[7])));
        float v2 = fmaf(cf[8], r, fmaf(cf[9],  g, fmaf(cf[10], bl, cf[11])));
        o0[px] = fminf(fmaxf(v0, 0.0f), 1.0f);
        o1[px] = fminf(fmaxf(v1, 0.0f), 1.0f);
        o2[px] = fminf(fmaxf(v2, 0.0f), 1.0f);
    }
}

// ---------------- driver (single stream, R8 topology) ----------------
extern "C" void kernel_launch(void* const* d_in, const int* in_sizes, int n_in,
                              void* d_out, int out_size) {
    const float* image_lowres  = (const float*)d_in[0];
    const float* image_fullres = (const float*)d_in[1];
    const float* sw0 = (const float*)d_in[2];  const float* sb0 = (const float*)d_in[3];
    const float* sw1 = (const float*)d_in[4];  const float* sb1 = (const float*)d_in[5];
    const float* sw2 = (const float*)d_in[6];  const float* sb2 = (const float*)d_in[7];
    const float* sw3 = (const float*)d_in[8];  const float* sb3 = (const float*)d_in[9];
    const float* gw0 = (const float*)d_in[10]; const float* gb0 = (const float*)d_in[11];
    const float* gw1 = (const float*)d_in[12]; const float* gb1 = (const float*)d_in[13];
    const float* fw0 = (const float*)d_in[14]; const float* fb0 = (const float*)d_in[15];
    const float* fw1 = (const float*)d_in[16]; const float* fb1 = (const float*)d_in[17];
    const float* fw2 = (const float*)d_in[18]; const float* fb2 = (const float*)d_in[19];
    const float* lw0 = (const float*)d_in[20]; const float* lb0 = (const float*)d_in[21];
    const float* lw1 = (const float*)d_in[22];
    const float* pw  = (const float*)d_in[23]; const float* pb  = (const float*)d_in[24];
    const float* ccm_w = (const float*)d_in[25]; const float* ccm_b = (const float*)d_in[26];
    const float* shifts = (const float*)d_in[27];
    const float* slopes = (const float*)d_in[28];
    const float* proj_w = (const float*)d_in[29];
    const float* proj_b = (const float*)d_in[30];

    int B = in_sizes[1] / (3 * 1024 * 1024);

    float *x1, *x2, *x3, *x4, *g1, *g2, *fc0, *fc1, *fc2, *loc1, *loc2, *co, *guide;
    cudaGetSymbolAddress((void**)&x1, d_x1);
    cudaGetSymbolAddress((void**)&x2, d_x2);
    cudaGetSymbolAddress((void**)&x3, d_x3);
    cudaGetSymbolAddress((void**)&x4, d_x4);
    cudaGetSymbolAddress((void**)&g1, d_g1);
    cudaGetSymbolAddress((void**)&g2, d_g2);
    cudaGetSymbolAddress((void**)&fc0, d_fc0);
    cudaGetSymbolAddress((void**)&fc1, d_fc1);
    cudaGetSymbolAddress((void**)&fc2, d_fc2);
    cudaGetSymbolAddress((void**)&loc1, d_loc1);
    cudaGetSymbolAddress((void**)&loc2, d_loc2);
    cudaGetSymbolAddress((void**)&co, d_co);
    cudaGetSymbolAddress((void**)&guide, d_guide);

    const int T = 256;
    auto blocks = [](int n, int t) { return (n + t - 1) / t; };

    guide_kernel<<<256, 256>>>(image_fullres, ccm_w, ccm_b, shifts, slopes,
                               proj_w, proj_b, guide, B);

    // ---- splat path ----
    {
        auto k = conv_tiled<3,256,256,8,2, 8,32, 1,2, 2,2, 1>;
        constexpr int sb = c_smem_tot(3,8,32,2,2,2);
        cudaFuncSetAttribute(k, cudaFuncAttributeMaxDynamicSharedMemorySize, sb);
        k<<<dim3(2,64,B), 256, sb>>>(image_lowres, sw0, sb0, x1);
    }
    {
        auto k = conv_tiled<8,128,128,16,2, 8,16, 1,2, 2,4, 1>;
        constexpr int sb = c_smem_tot(8,8,16,2,4,2);
        cudaFuncSetAttribute(k, cudaFuncAttributeMaxDynamicSharedMemorySize, sb);
        k<<<dim3(2,32,B), 256, sb>>>(x1, sw1, sb1, x2);
    }
    {
        auto k = conv_tiled<16,64,64,32,2, 8,16, 1,2, 1,4, 1>;
        constexpr int sb = c_smem_tot(16,8,16,2,4,1);
        cudaFuncSetAttribute(k, cudaFuncAttributeMaxDynamicSharedMemorySize, sb);
        k<<<dim3(8,8,B), 256, sb>>>(x2, sw2, sb2, x3);
    }
    {
        auto k = conv_tiled<32,32,32,64,2, 8,8, 1,2, 1,4, 1>;
        constexpr int sb = c_smem_tot(32,8,8,2,4,1);
        cudaFuncSetAttribute(k, cudaFuncAttributeMaxDynamicSharedMemorySize, sb);
        k<<<dim3(16,4,B), 128, sb>>>(x3, sw3, sb3, x4);
    }
    // ---- global path ----
    {
        auto k = conv_tiled<64,16,16,64,2, 8,8, 1,2, 1,4, 1>;
        constexpr int sb = c_smem_tot(64,8,8,2,4,1);
        cudaFuncSetAttribute(k, cudaFuncAttributeMaxDynamicSharedMemorySize, sb);
        k<<<dim3(16,1,B), 128, sb>>>(x4, gw0, gb0, g1);
    }
    {
        auto k = conv_tiled<64,8,8,64,2, 4,4, 1,2, 1,16, 1>;
        constexpr int sb = c_smem_tot(64,4,4,2,16,1);
        cudaFuncSetAttribute(k, cudaFuncAttributeMaxDynamicSharedMemorySize, sb);
        k<<<dim3(4,1,B), 128, sb>>>(g1, gw1, gb1, g2);
    }
    fc_kernel<<<blocks(B*256*32, T), T>>>(g2, fw0, fb0, fc0, B, 1024, 256, 1);
    fc_kernel<<<blocks(B*128*32, T), T>>>(fc0, fw1, fb1, fc1, B, 256, 128, 1);
    fc_kernel<<<blocks(B*64*32, T), T>>>(fc1, fw2, fb2, fc2, B, 128, 64, 0);
    // ---- local path ----
    {
        auto k = conv_tiled<64,16,16,64,1, 8,16, 1,2, 1,4, 1>;
        constexpr int sb = c_smem_tot(64,8,16,1,4,1);
        cudaFuncSetAttribute(k, cudaFuncAttributeMaxDynamicSharedMemorySize, sb);
        k<<<dim3(16,2,B), 256, sb>>>(x4, lw0, lb0, loc1);
    }
    {
        auto k = conv_tiled<64,16,16,64,1, 8,16, 1,2, 1,4, 0>;
        constexpr int sb = c_smem_tot(64,8,16,1,4,1);
        cudaFuncSetAttribute(k, cudaFuncAttributeMaxDynamicSharedMemorySize, sb);
        k<<<dim3(16,2,B), 256, sb>>>(loc1, lw1, nullptr, loc2);
    }
    // ---- fusion + 1x1 prediction ----
    co_kernel<<<blocks(B*96*64, T), T>>>(loc2, fc2, pw, pb, co, B);
    // ---- slice + apply ----
    {
        cudaFuncSetAttribute(slice_kernel, cudaFuncAttributeMaxDynamicSharedMemorySize, SLICE_SMEM);
        int pxPerBlock = 8192;
        dim3 g(HW_FULL / pxPerBlock, 1, B);
        slice_kernel<<<g, SLICE_WARPS*32, SLICE_SMEM>>>(image_fullres, guide, co,
                                                        (float*)d_out, pxPerBlock);
    }
}